// round 6
// baseline (speedup 1.0000x reference)
#include <cuda_runtime.h>
#include <cstdint>

#define BI 128
#define BT 128
#define RR 36
#define WW 50
#define DD 256
#define ILAMB 20.0f     // 1/0.05
#define EPSV 1e-6f

#define IP 2            // imgs per block (one pair per img)
#define JP 1            // caps per block (shared by both pairs)
#define NPAIR 2
#define KC 16           // K-chunk
#define NCHUNK (DD / KC)   // 16
#define MT 3            // 48 rows padded
#define NKS (KC / 8)    // 2 k-steps per chunk

#define STRIDE 24       // KC + 8 pad: LDS.64 phase-conflict-free (24g mod 32 = {0,24,16,8})
#define A_ROWS (IP * RR)             // 72 real rows staged
#define B_ROWS WW                    // 50 real rows staged
#define A_ROWS_PAD 48                // MT*16 per image
#define B_ROWS_PAD 56                // 7*8 per cap
#define A_FLOATS (IP * A_ROWS_PAD * STRIDE)   // 2304
#define B_FLOATS (B_ROWS_PAD * STRIDE)        // 1344
#define BUF_FLOATS (A_FLOATS + B_FLOATS)      // 3648
#define BUF_BYTES (BUF_FLOATS * 4)            // 14592

// Sinkhorn scratch (reuses the two staging buffers after GEMM)
#define KW 51                           // >= WW and odd (bank bijection)
#define KS_STRIDE (RR * KW)             // 1836
#define AL_OFF (NPAIR * KS_STRIDE)      // 3672
#define BE_OFF (AL_OFF + NPAIR * RR)    // 3744
#define RS_OFF (BE_OFF + NPAIR * WW)    // 3844  (4 reduce slots)

#define SMEM_FLOATS (2 * BUF_FLOATS)    // 7296 > 3848
#define SMEM_BYTES (SMEM_FLOATS * 4)    // 29184

__device__ float g_nimgs[BI * RR * DD];
__device__ float g_ncaps[BT * WW * DD];

__device__ __forceinline__ unsigned f2tf32(float x) {
    unsigned r;
    asm("cvt.rna.tf32.f32 %0, %1;" : "=r"(r) : "f"(x));
    return r;
}

__device__ __forceinline__ void cp16(uint32_t dst, const float* src) {
    asm volatile("cp.async.cg.shared.global [%0], [%1], 16;\n"
                 :: "r"(dst), "l"(src));
}

#define PAIR_BAR(p) asm volatile("bar.sync %0, %1;" :: "r"(1 + (p)), "r"(64) : "memory")

// k-permutation within each 8-group: pos = ((k&3)<<1) | ((k&7)>>2)
__device__ __forceinline__ int kperm(int k) {
    return (k & ~7) | (((k & 3) << 1) | ((k & 7) >> 2));
}

// ---------------------------------------------------------------------------
// Kernel 1: L2-normalize, round to tf32, store with permuted k-layout.
// ---------------------------------------------------------------------------
__global__ void norm_kernel(const float* __restrict__ imgs,
                            const float* __restrict__ caps) {
    int row  = blockIdx.x * 8 + (threadIdx.x >> 5);
    int lane = threadIdx.x & 31;
    const int n_img_rows = BI * RR;
    const int n_rows = n_img_rows + BT * WW;
    if (row >= n_rows) return;

    const float* src;
    float* dst;
    if (row < n_img_rows) {
        src = imgs + (size_t)row * DD;
        dst = g_nimgs + (size_t)row * DD;
    } else {
        int r2 = row - n_img_rows;
        src = caps + (size_t)r2 * DD;
        dst = g_ncaps + (size_t)r2 * DD;
    }
    const float4* s4 = reinterpret_cast<const float4*>(src);
    float4 v0 = s4[lane];
    float4 v1 = s4[lane + 32];
    float ss = v0.x * v0.x + v0.y * v0.y + v0.z * v0.z + v0.w * v0.w
             + v1.x * v1.x + v1.y * v1.y + v1.z * v1.z + v1.w * v1.w;
#pragma unroll
    for (int o = 16; o > 0; o >>= 1) ss += __shfl_xor_sync(0xffffffffu, ss, o);
    float inv = 1.0f / fmaxf(sqrtf(ss), 1e-8f);

    float a0[4] = {v0.x, v0.y, v0.z, v0.w};
    float a1[4] = {v1.x, v1.y, v1.z, v1.w};
    int k0 = 4 * lane;
#pragma unroll
    for (int m = 0; m < 4; ++m) {
        dst[kperm(k0 + m)]       = __uint_as_float(f2tf32(a0[m] * inv));
        dst[kperm(k0 + 128 + m)] = __uint_as_float(f2tf32(a1[m] * inv));
    }
}

// ---------------------------------------------------------------------------
// m16n8k8 tf32 mma
// ---------------------------------------------------------------------------
__device__ __forceinline__ void mma_tf32(float* c, const uint4& a, const uint2& b) {
    asm volatile(
        "mma.sync.aligned.m16n8k8.row.col.f32.tf32.tf32.f32 "
        "{%0,%1,%2,%3}, {%4,%5,%6,%7}, {%8,%9}, {%0,%1,%2,%3};\n"
        : "+f"(c[0]), "+f"(c[1]), "+f"(c[2]), "+f"(c[3])
        : "r"(a.x), "r"(a.y), "r"(a.z), "r"(a.w), "r"(b.x), "r"(b.y));
}

// Stage one K-chunk: A 72 rows (2 imgs), B 50 rows (1 cap), 4x16B per row.
__device__ __forceinline__ void stage_chunk(uint32_t sbase, int i0, int j0,
                                            int kc0, int tid) {
#pragma unroll
    for (int s = 0; s < 3; ++s) {
        int idx = tid + 128 * s;
        if (idx < A_ROWS * 4) {
            int row = idx >> 2, q = idx & 3;
            int im = (row >= RR) ? 1 : 0;
            int r = row - im * RR;
            const float* src = g_nimgs + ((size_t)(i0 + im) * RR + r) * DD + kc0 + q * 4;
            cp16(sbase + (im * A_ROWS_PAD + r) * (STRIDE * 4) + q * 16, src);
        }
    }
    uint32_t bbase = sbase + A_FLOATS * 4;
#pragma unroll
    for (int s = 0; s < 2; ++s) {
        int idx = tid + 128 * s;
        if (idx < B_ROWS * 4) {
            int row = idx >> 2, q = idx & 3;
            const float* src = g_ncaps + ((size_t)j0 * WW + row) * DD + kc0 + q * 4;
            cp16(bbase + row * (STRIDE * 4) + q * 16, src);
        }
    }
}

// ---------------------------------------------------------------------------
// Kernel 2: fused GEMM + Sinkhorn. 128 threads, 2 pairs, 2 warps per pair.
// Warp w: pair p = w>>1 (img i0+p), half h = w&1 (N-tiles h*4 .. h*4+(3-h)).
// ---------------------------------------------------------------------------
__global__ __launch_bounds__(128, 5)
void wass_kernel(const int* __restrict__ img_lens,
                 const int* __restrict__ cap_lens,
                 float* __restrict__ out) {
    extern __shared__ float smem[];
    const int i0 = blockIdx.y * IP;
    const int j0 = blockIdx.x;
    const int tid = threadIdx.x;
    const int lane = tid & 31;
    const int wid = tid >> 5;
    const int gid = lane >> 2;
    const int tig = lane & 3;
    const int p = wid >> 1;
    const int h = wid & 1;
    const int nbase = h * 4;
    const int ntw = 4 - h;       // 4 or 3 N-tiles

    uint32_t sb;
    asm("{ .reg .u64 t; cvta.to.shared.u64 t, %1; cvt.u32.u64 %0, t; }"
        : "=r"(sb) : "l"(smem));

    float C[MT][4][4];
#pragma unroll
    for (int mt = 0; mt < MT; ++mt)
#pragma unroll
        for (int nt = 0; nt < 4; ++nt)
#pragma unroll
            for (int c = 0; c < 4; ++c) C[mt][nt][c] = 0.0f;

    stage_chunk(sb, i0, j0, 0, tid);
    asm volatile("cp.async.commit_group;" ::: "memory");

    for (int ch = 0; ch < NCHUNK; ++ch) {
        if (ch + 1 < NCHUNK) {
            stage_chunk(sb + ((ch + 1) & 1) * BUF_BYTES, i0, j0, (ch + 1) * KC, tid);
            asm volatile("cp.async.commit_group;" ::: "memory");
            asm volatile("cp.async.wait_group 1;" ::: "memory");
        } else {
            asm volatile("cp.async.wait_group 0;" ::: "memory");
        }
        __syncthreads();

        const float* Abuf = smem + (ch & 1) * BUF_FLOATS + p * (A_ROWS_PAD * STRIDE);
        const float* Bbuf = smem + (ch & 1) * BUF_FLOATS + A_FLOATS;
#pragma unroll
        for (int ks = 0; ks < NKS; ++ks) {
            uint4 a[MT];
#pragma unroll
            for (int mt = 0; mt < MT; ++mt) {
                const float* pa = Abuf + (mt * 16 + gid) * STRIDE + ks * 8 + 2 * tig;
                float2 v1 = *reinterpret_cast<const float2*>(pa);
                float2 v2 = *reinterpret_cast<const float2*>(pa + 8 * STRIDE);
                a[mt].x = __float_as_uint(v1.x);   // k = tig
                a[mt].y = __float_as_uint(v2.x);   // row+8, k = tig
                a[mt].z = __float_as_uint(v1.y);   // k = tig+4
                a[mt].w = __float_as_uint(v2.y);   // row+8, k = tig+4
            }
#pragma unroll
            for (int nt = 0; nt < 4; ++nt) {
                if (nt < ntw) {
                    const float* q = Bbuf + ((nbase + nt) * 8 + gid) * STRIDE
                                   + ks * 8 + 2 * tig;
                    float2 bv = *reinterpret_cast<const float2*>(q);
                    uint2 b;
                    b.x = __float_as_uint(bv.x);
                    b.y = __float_as_uint(bv.y);
#pragma unroll
                    for (int mt = 0; mt < MT; ++mt) mma_tf32(C[mt][nt], a[mt], b);
                }
            }
        }
        __syncthreads();   // buffer (ch&1) free for restage / Sinkhorn reuse
    }

    // ---------------- Sinkhorn (2 warps = 64 threads per pair) ----------------
    const int i = i0 + p;
    const int j = j0;
    const int Ri = img_lens[i];
    const int Wj = cap_lens[j];
    float* Kp  = smem + p * KS_STRIDE;       // [36][51]
    float* alp = smem + AL_OFF + p * RR;     // [36]
    float* bet = smem + BE_OFF + p * WW;     // [50]
    float* red = smem + RS_OFF;              // [4]
    const int t64 = h * 32 + lane;           // 0..63 within pair

    // K = exp((s-1)/lambda) masked; partial total sum per warp
    float tsum = 0.0f;
#pragma unroll
    for (int mt = 0; mt < MT; ++mt)
#pragma unroll
        for (int nt = 0; nt < 4; ++nt) {
            if (nt < ntw) {
#pragma unroll
                for (int c = 0; c < 4; ++c) {
                    int r = mt * 16 + gid + ((c >> 1) << 3);
                    int w = (nbase + nt) * 8 + (tig << 1) + (c & 1);
                    if (r < Ri && w < Wj) {
                        float s = C[mt][nt][c];
                        float k = __expf(ILAMB * s - ILAMB);
                        Kp[r * KW + w] = k;
                        tsum += k;
                    }
                }
            }
        }
#pragma unroll
    for (int o = 16; o > 0; o >>= 1) tsum += __shfl_xor_sync(0xffffffffu, tsum, o);
    if (lane == 0) red[wid] = tsum;
    // init marginals
    if (t64 < RR) alp[t64] = 0.0f;   // placeholder, set below after reduce
    if (t64 < WW) bet[t64] = 1.0f;
    PAIR_BAR(p);

    float alpha0 = 1.0f / (red[2 * p] + red[2 * p + 1] + EPSV);
    if (t64 < RR) alp[t64] = alpha0;
    const float rm = 1.0f / (float)Ri;
    const float cm = 1.0f / (float)Wj;
    PAIR_BAR(p);

#pragma unroll
    for (int it = 0; it < 3; ++it) {
        if (t64 < Ri) {
            float dot = 0.0f;
            for (int w = 0; w < Wj; ++w) dot += Kp[t64 * KW + w] * bet[w];
            float a = alp[t64];
            alp[t64] = a * (rm / (a * dot + EPSV));
        }
        PAIR_BAR(p);
        if (t64 < Wj) {
            float dot = 0.0f;
            for (int r = 0; r < Ri; ++r) dot += Kp[r * KW + t64] * alp[r];
            float b = bet[t64];
            bet[t64] = b * (cm / (b * dot + EPSV));
        }
        PAIR_BAR(p);
    }

    // final: sum s * K * alpha_r * beta_w over valid entries
    float acc = 0.0f;
#pragma unroll
    for (int mt = 0; mt < MT; ++mt)
#pragma unroll
        for (int nt = 0; nt < 4; ++nt) {
            if (nt < ntw) {
#pragma unroll
                for (int c = 0; c < 4; ++c) {
                    int r = mt * 16 + gid + ((c >> 1) << 3);
                    int w = (nbase + nt) * 8 + (tig << 1) + (c & 1);
                    if (r < Ri && w < Wj) {
                        float s = C[mt][nt][c];
                        float k = __expf(ILAMB * s - ILAMB);
                        acc += s * k * alp[r] * bet[w];
                    }
                }
            }
        }
#pragma unroll
    for (int o = 16; o > 0; o >>= 1) acc += __shfl_xor_sync(0xffffffffu, acc, o);
    if (lane == 0) red[wid] = acc;
    PAIR_BAR(p);
    if (h == 0 && lane == 0)
        out[i * BT + j] = red[2 * p] + red[2 * p + 1];
}

// ---------------------------------------------------------------------------
extern "C" void kernel_launch(void* const* d_in, const int* in_sizes, int n_in,
                              void* d_out, int out_size) {
    const float* imgs = (const float*)d_in[0];
    const float* caps = (const float*)d_in[1];
    const int* img_lens = (const int*)d_in[2];
    const int* cap_lens = (const int*)d_in[3];
    float* out = (float*)d_out;

    cudaFuncSetAttribute(wass_kernel,
                         cudaFuncAttributeMaxDynamicSharedMemorySize, SMEM_BYTES);

    int n_rows = BI * RR + BT * WW;
    int nblk = (n_rows + 7) / 8;
    norm_kernel<<<nblk, 256>>>(imgs, caps);

    dim3 grid(BT, BI / IP);  // (128, 64)
    wass_kernel<<<grid, 128, SMEM_BYTES>>>(img_lens, cap_lens, out);
}

// round 7
// speedup vs baseline: 1.3127x; 1.3127x over previous
#include <cuda_runtime.h>
#include <cstdint>

#define BI 128
#define BT 128
#define RR 36
#define WW 50
#define DD 256
#define ILAMB 20.0f     // 1/0.05
#define EPSV 1e-6f

#define IP 2            // imgs per block
#define JP 4            // caps per block
#define NPAIR 8         // IP*JP
#define KC 32           // K-chunk
#define NCHUNK (DD / KC)   // 8
#define MT 3            // 48 rows padded
#define NT 7            // 56 cols padded
#define NKS (KC / 8)    // 4 k-steps per chunk

// Pre-baked fragment-quad layouts in gmem (ks-major => chunk-contiguous):
// A quad (16B) at ((ks*3+mt)*32 + gid*4+tig): {A[r][k], A[r+8][k], A[r][k+4], A[r+8][k+4]}
//   r = mt*16+gid(+8), k = ks*8+tig(+4). 48 padded rows/img.
// B pair (8B)  at ((ks*7+nt)*32 + gid*4+tig): {B[n][k], B[n][k+4]}, n = nt*8+gid. 56 padded rows/cap.
#define A_IMG_FLOATS (32 * MT * 128)    // 12288 per image
#define B_CAP_FLOATS (32 * NT * 64)     // 14336 per cap
#define A_CHUNK_FLOATS (NKS * MT * 128) // 1536 per image per chunk
#define B_CHUNK_FLOATS (NKS * NT * 64)  // 1792 per cap per chunk
#define A_REG_FLOATS (IP * A_CHUNK_FLOATS)  // 3072
#define B_REG_FLOATS (JP * B_CHUNK_FLOATS)  // 7168
#define BUF_FLOATS (A_REG_FLOATS + B_REG_FLOATS)  // 10240
#define BUF_BYTES (BUF_FLOATS * 4)                // 40960

// Sinkhorn scratch (reuses the two staging buffers after GEMM)
#define KW 57                           // >= WW, odd: conflict-free col walks
#define KS_STRIDE (RR * KW)             // 2052
#define KS_FLOATS (NPAIR * KS_STRIDE)   // 16416
#define AL_OFF KS_FLOATS
#define BE_OFF (KS_FLOATS + NPAIR * RR)
#define SINK_FLOATS (KS_FLOATS + NPAIR * RR + NPAIR * WW)  // 17104

#define SMEM_FLOATS (2 * BUF_FLOATS)    // 20480 > 17104
#define SMEM_BYTES (SMEM_FLOATS * 4)    // 81920

__device__ float g_aq[BI * A_IMG_FLOATS];
__device__ float g_bq[BT * B_CAP_FLOATS];

__device__ __forceinline__ unsigned f2tf32(float x) {
    unsigned r;
    asm("cvt.rna.tf32.f32 %0, %1;" : "=r"(r) : "f"(x));
    return r;
}

__device__ __forceinline__ void cp16(uint32_t dst, const float* src) {
    asm volatile("cp.async.cg.shared.global [%0], [%1], 16;\n"
                 :: "r"(dst), "l"(src));
}

// ---------------------------------------------------------------------------
// Kernel 1: L2-normalize rows, round to tf32, scatter into fragment-quad
// layout. One warp per PADDED row (pad rows write zeros). lane = ks block.
// ---------------------------------------------------------------------------
__global__ void norm_kernel(const float* __restrict__ imgs,
                            const float* __restrict__ caps) {
    int pr   = blockIdx.x * 8 + (threadIdx.x >> 5);
    int lane = threadIdx.x & 31;
    const int A_PROWS = BI * 48;        // 6144
    const int TOT = A_PROWS + BT * 56;  // 13312
    if (pr >= TOT) return;

    float vals[8];
    if (pr < A_PROWS) {
        int i = pr / 48, r = pr - i * 48;
        if (r < RR) {
            const float4* s4 = reinterpret_cast<const float4*>(
                imgs + ((size_t)i * RR + r) * DD);
            float4 v0 = s4[2 * lane], v1 = s4[2 * lane + 1];
            float ss = v0.x * v0.x + v0.y * v0.y + v0.z * v0.z + v0.w * v0.w
                     + v1.x * v1.x + v1.y * v1.y + v1.z * v1.z + v1.w * v1.w;
#pragma unroll
            for (int o = 16; o > 0; o >>= 1)
                ss += __shfl_xor_sync(0xffffffffu, ss, o);
            float inv = 1.0f / fmaxf(sqrtf(ss), 1e-8f);
            vals[0] = __uint_as_float(f2tf32(v0.x * inv));
            vals[1] = __uint_as_float(f2tf32(v0.y * inv));
            vals[2] = __uint_as_float(f2tf32(v0.z * inv));
            vals[3] = __uint_as_float(f2tf32(v0.w * inv));
            vals[4] = __uint_as_float(f2tf32(v1.x * inv));
            vals[5] = __uint_as_float(f2tf32(v1.y * inv));
            vals[6] = __uint_as_float(f2tf32(v1.z * inv));
            vals[7] = __uint_as_float(f2tf32(v1.w * inv));
        } else {
#pragma unroll
            for (int y = 0; y < 8; ++y) vals[y] = 0.0f;
        }
        int mt = r >> 4, x = r & 15, g = x & 7, hi = x >> 3;
        float* dst = g_aq + (size_t)i * A_IMG_FLOATS;
#pragma unroll
        for (int y = 0; y < 8; ++y) {
            int tg = y & 3, khi = y >> 2;
            dst[((lane * 3 + mt) * 32 + g * 4 + tg) * 4 + khi * 2 + hi] = vals[y];
        }
    } else {
        int pr2 = pr - A_PROWS;
        int j = pr2 / 56, w = pr2 - j * 56;
        if (w < WW) {
            const float4* s4 = reinterpret_cast<const float4*>(
                caps + ((size_t)j * WW + w) * DD);
            float4 v0 = s4[2 * lane], v1 = s4[2 * lane + 1];
            float ss = v0.x * v0.x + v0.y * v0.y + v0.z * v0.z + v0.w * v0.w
                     + v1.x * v1.x + v1.y * v1.y + v1.z * v1.z + v1.w * v1.w;
#pragma unroll
            for (int o = 16; o > 0; o >>= 1)
                ss += __shfl_xor_sync(0xffffffffu, ss, o);
            float inv = 1.0f / fmaxf(sqrtf(ss), 1e-8f);
            vals[0] = __uint_as_float(f2tf32(v0.x * inv));
            vals[1] = __uint_as_float(f2tf32(v0.y * inv));
            vals[2] = __uint_as_float(f2tf32(v0.z * inv));
            vals[3] = __uint_as_float(f2tf32(v0.w * inv));
            vals[4] = __uint_as_float(f2tf32(v1.x * inv));
            vals[5] = __uint_as_float(f2tf32(v1.y * inv));
            vals[6] = __uint_as_float(f2tf32(v1.z * inv));
            vals[7] = __uint_as_float(f2tf32(v1.w * inv));
        } else {
#pragma unroll
            for (int y = 0; y < 8; ++y) vals[y] = 0.0f;
        }
        int nt = w >> 3, g = w & 7;
        float* dst = g_bq + (size_t)j * B_CAP_FLOATS;
#pragma unroll
        for (int y = 0; y < 8; ++y) {
            int tg = y & 3, khi = y >> 2;
            dst[((lane * 7 + nt) * 32 + g * 4 + tg) * 2 + khi] = vals[y];
        }
    }
}

// ---------------------------------------------------------------------------
// m16n8k8 tf32 mma
// ---------------------------------------------------------------------------
__device__ __forceinline__ void mma_tf32(float* c, const uint4& a, const uint2& b) {
    asm volatile(
        "mma.sync.aligned.m16n8k8.row.col.f32.tf32.tf32.f32 "
        "{%0,%1,%2,%3}, {%4,%5,%6,%7}, {%8,%9}, {%0,%1,%2,%3};\n"
        : "+f"(c[0]), "+f"(c[1]), "+f"(c[2]), "+f"(c[3])
        : "r"(a.x), "r"(a.y), "r"(a.z), "r"(a.w), "r"(b.x), "r"(b.y));
}

// Stage one chunk: pure bulk copy, constant strides, zero index math.
__device__ __forceinline__ void stage(const float* srcA, uint32_t dstA,
                                      const float* srcB, uint32_t dstB) {
#pragma unroll
    for (int s = 0; s < 3; ++s)
        cp16(dstA + s * 2048, srcA + s * 512);   // 128 quads per step
#pragma unroll
    for (int s = 0; s < 7; ++s)
        cp16(dstB + s * 1024, srcB + s * 256);   // 64 quads per step
}

// ---------------------------------------------------------------------------
// Kernel 2: fused GEMM (tf32 mma.sync, cp.async double-buffered) + Sinkhorn.
// Block = IP imgs x JP caps; warp w owns pair (ii = w>>2, jj = w&3).
// ---------------------------------------------------------------------------
__global__ __launch_bounds__(256, 2)
void wass_kernel(const int* __restrict__ img_lens,
                 const int* __restrict__ cap_lens,
                 float* __restrict__ out) {
    extern __shared__ float smem[];
    const int i0 = blockIdx.y * IP;
    const int j0 = blockIdx.x * JP;
    const int tid = threadIdx.x;
    const int lane = tid & 31;
    const int wid = tid >> 5;
    const int gid = lane >> 2;
    const int tig = lane & 3;
    const int ii = wid >> 2;
    const int jj = wid & 3;

    uint32_t sb;
    asm("{ .reg .u64 t; cvta.to.shared.u64 t, %1; cvt.u32.u64 %0, t; }"
        : "=r"(sb) : "l"(smem));

    // --- per-thread staging assignment (fixed for all chunks) ---
    const int imA = tid >> 7, tA = tid & 127;       // A: img = tid/128, 3 quads @ +128
    const int capB = tid >> 6, tB = tid & 63;       // B: cap = tid/64,  7 quads @ +64
    const float* srcA = g_aq + (size_t)(i0 + imA) * A_IMG_FLOATS + tA * 4;
    const float* srcB = g_bq + (size_t)(j0 + capB) * B_CAP_FLOATS + tB * 4;
    const uint32_t dstA = sb + imA * (A_CHUNK_FLOATS * 4) + tA * 16;
    const uint32_t dstB = sb + A_REG_FLOATS * 4 + capB * (B_CHUNK_FLOATS * 4) + tB * 16;

    float C[MT][NT][4];
#pragma unroll
    for (int mt = 0; mt < MT; ++mt)
#pragma unroll
        for (int nt = 0; nt < NT; ++nt)
#pragma unroll
            for (int c = 0; c < 4; ++c) C[mt][nt][c] = 0.0f;

    // prologue: stage chunk 0 into buffer 0
    stage(srcA, dstA, srcB, dstB);
    asm volatile("cp.async.commit_group;" ::: "memory");
    srcA += A_CHUNK_FLOATS;
    srcB += B_CHUNK_FLOATS;

    for (int ch = 0; ch < NCHUNK; ++ch) {
        if (ch + 1 < NCHUNK) {
            uint32_t off = ((ch + 1) & 1) * BUF_BYTES;
            stage(srcA, dstA + off, srcB, dstB + off);
            asm volatile("cp.async.commit_group;" ::: "memory");
            srcA += A_CHUNK_FLOATS;
            srcB += B_CHUNK_FLOATS;
            asm volatile("cp.async.wait_group 1;" ::: "memory");
        } else {
            asm volatile("cp.async.wait_group 0;" ::: "memory");
        }
        __syncthreads();

        const float4* Aq = reinterpret_cast<const float4*>(
            smem + (ch & 1) * BUF_FLOATS) + ii * (A_CHUNK_FLOATS / 4);
        const float2* Bq = reinterpret_cast<const float2*>(
            smem + (ch & 1) * BUF_FLOATS + A_REG_FLOATS) + jj * (B_CHUNK_FLOATS / 2);
#pragma unroll
        for (int ks = 0; ks < NKS; ++ks) {
            uint4 a[MT];
#pragma unroll
            for (int mt = 0; mt < MT; ++mt) {
                float4 av = Aq[(ks * 3 + mt) * 32 + lane];   // one LDS.128
                a[mt].x = __float_as_uint(av.x);
                a[mt].y = __float_as_uint(av.y);
                a[mt].z = __float_as_uint(av.z);
                a[mt].w = __float_as_uint(av.w);
            }
#pragma unroll
            for (int nt = 0; nt < NT; ++nt) {
                float2 bv = Bq[(ks * 7 + nt) * 32 + lane];   // one LDS.64
                uint2 b;
                b.x = __float_as_uint(bv.x);
                b.y = __float_as_uint(bv.y);
#pragma unroll
                for (int mt = 0; mt < MT; ++mt) mma_tf32(C[mt][nt], a[mt], b);
            }
        }
        __syncthreads();   // buffer (ch&1) free for restage / Sinkhorn reuse
    }

    // ---------------- Sinkhorn (warp-private per pair) ----------------
    const int i = i0 + ii;
    const int j = j0 + jj;
    const int Ri = img_lens[i];
    const int Wj = cap_lens[j];
    float* Kp = smem + wid * KS_STRIDE;        // [36][57]
    float* alp = smem + AL_OFF + wid * RR;     // [36]
    float* bet = smem + BE_OFF + wid * WW;     // [50]

    // K = exp((s-1)/lambda) masked; accumulate total sum
    float tsum = 0.0f;
#pragma unroll
    for (int mt = 0; mt < MT; ++mt)
#pragma unroll
        for (int nt = 0; nt < NT; ++nt)
#pragma unroll
            for (int c = 0; c < 4; ++c) {
                int r = mt * 16 + gid + ((c >> 1) << 3);
                int w = nt * 8 + (tig << 1) + (c & 1);
                if (r < Ri && w < Wj) {
                    float s = C[mt][nt][c];
                    float k = __expf(ILAMB * s - ILAMB);
                    Kp[r * KW + w] = k;
                    tsum += k;
                }
            }
#pragma unroll
    for (int o = 16; o > 0; o >>= 1) tsum += __shfl_xor_sync(0xffffffffu, tsum, o);
    float alpha0 = 1.0f / (tsum + EPSV);

    for (int r = lane; r < Ri; r += 32) alp[r] = alpha0;
    for (int w = lane; w < Wj; w += 32) bet[w] = 1.0f;
    const float rm = 1.0f / (float)Ri;
    const float cm = 1.0f / (float)Wj;
    __syncwarp();

#pragma unroll
    for (int it = 0; it < 3; ++it) {
        for (int r = lane; r < Ri; r += 32) {
            float dot = 0.0f;
            for (int w = 0; w < Wj; ++w) dot += Kp[r * KW + w] * bet[w];
            float a = alp[r];
            alp[r] = a * (rm / (a * dot + EPSV));
        }
        __syncwarp();
        for (int w = lane; w < Wj; w += 32) {
            float dot = 0.0f;
            for (int r = 0; r < Ri; ++r) dot += Kp[r * KW + w] * alp[r];
            float b = bet[w];
            bet[w] = b * (cm / (b * dot + EPSV));
        }
        __syncwarp();
    }

    // final: sum s * K * alpha_r * beta_w over valid entries
    float acc = 0.0f;
#pragma unroll
    for (int mt = 0; mt < MT; ++mt)
#pragma unroll
        for (int nt = 0; nt < NT; ++nt)
#pragma unroll
            for (int c = 0; c < 4; ++c) {
                int r = mt * 16 + gid + ((c >> 1) << 3);
                int w = nt * 8 + (tig << 1) + (c & 1);
                if (r < Ri && w < Wj) {
                    float s = C[mt][nt][c];
                    float k = __expf(ILAMB * s - ILAMB);
                    acc += s * k * alp[r] * bet[w];
                }
            }
#pragma unroll
    for (int o = 16; o > 0; o >>= 1) acc += __shfl_xor_sync(0xffffffffu, acc, o);
    if (lane == 0) out[i * BT + j] = acc;
}

// ---------------------------------------------------------------------------
extern "C" void kernel_launch(void* const* d_in, const int* in_sizes, int n_in,
                              void* d_out, int out_size) {
    const float* imgs = (const float*)d_in[0];
    const float* caps = (const float*)d_in[1];
    const int* img_lens = (const int*)d_in[2];
    const int* cap_lens = (const int*)d_in[3];
    float* out = (float*)d_out;

    cudaFuncSetAttribute(wass_kernel,
                         cudaFuncAttributeMaxDynamicSharedMemorySize, SMEM_BYTES);

    int n_prows = BI * 48 + BT * 56;   // 13312 padded rows
    int nblk = (n_prows + 7) / 8;
    norm_kernel<<<nblk, 256>>>(imgs, caps);

    dim3 grid(BT / JP, BI / IP);  // (32, 64)
    wass_kernel<<<grid, 256, SMEM_BYTES>>>(img_lens, cap_lens, out);
}